// round 9
// baseline (speedup 1.0000x reference)
#include <cuda_runtime.h>
#include <cuda_bf16.h>
#include <math_constants.h>
#include <mma.h>

using namespace nvcuda;

// Problem constants
#define B_    128
#define T_    1024
#define D_    512
#define V_    128
#define L_    128
#define S_    257           // 2L+1
#define BLANK_ 127          // V-1
#define EPS_  1e-7f
#define NEG_  (-1e30f)
#define LN2_  0.6931471805599453f

// GEMM tiling
#define BM 128
#define BN 128
#define BK 16
#define NCHUNK (D_ / BK)    // 32
#define APAD 4
#define BPAD 4

// Scratch: log2(softmax prob + eps) [B,T,V] fp32 (64 MB), per-example losses
static __device__ float g_lp[B_ * T_ * V_];
static __device__ float g_loss[B_];

__device__ __forceinline__ float fexp2(float x) {
    float y; asm("ex2.approx.ftz.f32 %0, %1;" : "=f"(y) : "f"(x)); return y;
}

__device__ __forceinline__ void cp16(void* dst_smem, const void* src) {
    unsigned d = (unsigned)__cvta_generic_to_shared(dst_smem);
    asm volatile("cp.async.ca.shared.global [%0], [%1], 16;\n" :: "r"(d), "l"(src));
}
__device__ __forceinline__ void cp_commit() {
    asm volatile("cp.async.commit_group;\n");
}

// ---------------------------------------------------------------------------
// Kernel 1: tf32 WMMA GEMM (logits = X @ W + b) + softmax -> g_lp = log2(p+eps)
// M = 131072, N = 128, K = 512. cp.async 2-stage pipeline staging raw fp32
// (no conversion on the load path; tf32 MMA reads fp32 smem). Block 128x128,
// BK=16, 8 warps (4M x 2N), warp tile 32x64. Epilogue reuses stage smem (union).
// ---------------------------------------------------------------------------
struct Stage {
    float A[BM][BK + APAD];   // 128 x 20
    float B[BK][BN + BPAD];   //  16 x 132
};

__global__ __launch_bounds__(256) void gemm_softmax_kernel(
    const float* __restrict__ X, const float* __restrict__ W,
    const float* __restrict__ bias)
{
    __shared__ union {
        Stage st[2];              // 2 x 18688 B = 37376 B
        float Cs[32][BN + BPAD];  // 16896 B (epilogue reuse)
    } smem;

    const int tid = threadIdx.x;
    const int wid = tid >> 5;
    const int warp_m = wid & 3;       // 0..3
    const int warp_n = wid >> 2;      // 0..1
    const int rowBase = blockIdx.x * BM;

    wmma::fragment<wmma::accumulator, 16, 16, 8, float> cfrag[2][4];
#pragma unroll
    for (int i = 0; i < 2; ++i)
#pragma unroll
        for (int j = 0; j < 4; ++j) wmma::fill_fragment(cfrag[i][j], 0.f);

    // cp.async mapping: A 128x16 (2 threads/row, 8 floats each);
    //                   B  16x128 (16 threads/row, 8 floats each)
    const int ar = tid >> 1;
    const int ac = (tid & 1) * 8;
    const int br = tid >> 4;
    const int bc = (tid & 15) * 8;
    const float* Ap = X + (size_t)(rowBase + ar) * D_ + ac;
    const float* Bp = W + (size_t)br * V_ + bc;

    // Prologue: issue chunks 0 and 1
#pragma unroll
    for (int p = 0; p < 2; ++p) {
        Stage& st = smem.st[p];
        cp16(&st.A[ar][ac],     Ap + p * BK);
        cp16(&st.A[ar][ac + 4], Ap + p * BK + 4);
        cp16(&st.B[br][bc],     Bp + (size_t)p * BK * V_);
        cp16(&st.B[br][bc + 4], Bp + (size_t)p * BK * V_ + 4);
        cp_commit();
    }

    for (int c = 0; c < NCHUNK; ++c) {
        asm volatile("cp.async.wait_group 1;\n");
        __syncthreads();
        Stage& st = smem.st[c & 1];

#pragma unroll
        for (int kk = 0; kk < BK; kk += 8) {
            wmma::fragment<wmma::matrix_a, 16, 16, 8, wmma::precision::tf32, wmma::row_major> af[2];
            wmma::fragment<wmma::matrix_b, 16, 16, 8, wmma::precision::tf32, wmma::row_major> bf[4];
#pragma unroll
            for (int i = 0; i < 2; ++i) {
                wmma::load_matrix_sync(af[i], &st.A[warp_m * 32 + i * 16][kk], BK + APAD);
#pragma unroll
                for (int e = 0; e < af[i].num_elements; ++e)
                    af[i].x[e] = wmma::__float_to_tf32(af[i].x[e]);
            }
#pragma unroll
            for (int j = 0; j < 4; ++j) {
                wmma::load_matrix_sync(bf[j], &st.B[kk][warp_n * 64 + j * 16], BN + BPAD);
#pragma unroll
                for (int e = 0; e < bf[j].num_elements; ++e)
                    bf[j].x[e] = wmma::__float_to_tf32(bf[j].x[e]);
            }
#pragma unroll
            for (int i = 0; i < 2; ++i)
#pragma unroll
                for (int j = 0; j < 4; ++j)
                    wmma::mma_sync(cfrag[i][j], af[i], bf[j], cfrag[i][j]);
        }
        __syncthreads();   // all reads of this stage done before refill

        if (c + 2 < NCHUNK) {
            const int k0 = (c + 2) * BK;
            Stage& nst = smem.st[c & 1];
            cp16(&nst.A[ar][ac],     Ap + k0);
            cp16(&nst.A[ar][ac + 4], Ap + k0 + 4);
            cp16(&nst.B[br][bc],     Bp + (size_t)k0 * V_);
            cp16(&nst.B[br][bc + 4], Bp + (size_t)k0 * V_ + 4);
        }
        cp_commit();       // empty group when nothing issued keeps counts uniform
    }

    // Epilogue: 4 passes of 32 rows through Cs (aliases stage smem; all stage
    // reads completed at the loop's final barrier). Softmax, write log2(p+eps).
    const int tx = tid & 15;
    const int ty = tid >> 4;
    float bb[8];
#pragma unroll
    for (int j = 0; j < 8; ++j) bb[j] = bias[tx * 8 + j];

    for (int wm = 0; wm < 4; ++wm) {
        if (warp_m == wm) {
#pragma unroll
            for (int i = 0; i < 2; ++i)
#pragma unroll
                for (int j = 0; j < 4; ++j)
                    wmma::store_matrix_sync(&smem.Cs[i * 16][warp_n * 64 + j * 16],
                                            cfrag[i][j], BN + BPAD, wmma::mem_row_major);
        }
        __syncthreads();
#pragma unroll
        for (int r = 0; r < 2; ++r) {
            const int row = ty * 2 + r;
            float l[8];
            float rmax = -CUDART_INF_F;
#pragma unroll
            for (int j = 0; j < 8; ++j) {
                l[j] = smem.Cs[row][tx * 8 + j] + bb[j];
                rmax = fmaxf(rmax, l[j]);
            }
#pragma unroll
            for (int m = 1; m <= 8; m <<= 1)
                rmax = fmaxf(rmax, __shfl_xor_sync(0xFFFFFFFFu, rmax, m));
            float s = 0.f;
#pragma unroll
            for (int j = 0; j < 8; ++j) { l[j] = __expf(l[j] - rmax); s += l[j]; }
#pragma unroll
            for (int m = 1; m <= 8; m <<= 1)
                s += __shfl_xor_sync(0xFFFFFFFFu, s, m);
            float invs = 1.f / s;
            float* orow = g_lp + (size_t)(rowBase + wm * 32 + row) * V_ + tx * 8;
            float4 o0, o1;
            o0.x = __log2f(l[0] * invs + EPS_); o0.y = __log2f(l[1] * invs + EPS_);
            o0.z = __log2f(l[2] * invs + EPS_); o0.w = __log2f(l[3] * invs + EPS_);
            o1.x = __log2f(l[4] * invs + EPS_); o1.y = __log2f(l[5] * invs + EPS_);
            o1.z = __log2f(l[6] * invs + EPS_); o1.w = __log2f(l[7] * invs + EPS_);
            *(float4*)orow = o0;
            *(float4*)(orow + 4) = o1;
        }
        __syncthreads();
    }
}

// ---------------------------------------------------------------------------
// Kernel 2: CTC forward DP, log2 domain, REGISTER-resident alpha.
// One block per example, 288 threads (9 warps), thread s owns state s (<257).
// In-warp neighbors via shfl_up (on pre-barrier registers); cross-warp
// boundary (2 values/warp) via tiny double-buffered smem, drained by the
// per-step __syncthreads. Emissions via 8-deep statically-indexed FIFO.
// ---------------------------------------------------------------------------
__global__ __launch_bounds__(288) void ctc_kernel(
    const int* __restrict__ targets, const int* __restrict__ tlen)
{
    __shared__ float bnd[2][10][2];   // [parity][warp(consumer idx)][a30,a31]
    __shared__ int   exts[S_];
    __shared__ float afin[S_];

    const int b    = blockIdx.x;
    const int tid  = threadIdx.x;
    const int warp = tid >> 5;        // 0..8
    const int lane = tid & 31;
    const bool act = (tid < S_);
    const float* LP = g_lp + (size_t)b * T_ * V_;

    if (act) exts[tid] = (tid & 1) ? targets[b * L_ + (tid >> 1)] : BLANK_;
    if (tid == 0) {
        bnd[0][0][0] = NEG_; bnd[0][0][1] = NEG_;   // left sentinel for warp 0
        bnd[1][0][0] = NEG_; bnd[1][0][1] = NEG_;
    }
    __syncthreads();

    int  myext  = BLANK_;
    bool allow2 = false;
    if (act) {
        myext  = exts[tid];
        allow2 = (tid & 1) && (tid >= 2) && (myext != exts[tid - 2]);
    }

    // t = 0 init + emission FIFO for t = 1..8
    float alpha = (act && tid < 2) ? LP[myext] : NEG_;
    float e[8];
#pragma unroll
    for (int j = 0; j < 8; ++j) e[j] = LP[(size_t)(1 + j) * V_ + myext];

    // Publish t=0 boundary (parity 0)
    if (lane >= 30 && warp < 8) bnd[0][warp + 1][lane - 30] = alpha;
    __syncthreads();
    float bndL0 = bnd[0][warp][0];
    float bndL1 = bnd[0][warp][1];

#define CTC_STEP(T_IDX, EJ)                                                  \
    {                                                                        \
        float a1 = __shfl_up_sync(0xFFFFFFFFu, alpha, 1);                    \
        float a2 = __shfl_up_sync(0xFFFFFFFFu, alpha, 2);                    \
        if (lane == 0) { a1 = bndL1; a2 = bndL0; }                           \
        else if (lane == 1) { a2 = bndL1; }                                  \
        float a2v = allow2 ? a2 : NEG_;                                      \
        float m  = fmaxf(fmaxf(alpha, a1), a2v);                             \
        float s  = fexp2(alpha - m) + fexp2(a1 - m) + fexp2(a2v - m);        \
        alpha = m + __log2f(s) + (EJ);                                       \
        if (lane >= 30 && warp < 8) bnd[(T_IDX) & 1][warp + 1][lane - 30] = alpha; \
        __syncthreads();                                                     \
        bndL0 = bnd[(T_IDX) & 1][warp][0];                                   \
        bndL1 = bnd[(T_IDX) & 1][warp][1];                                   \
    }

    // Main chunks: t0 = 1, 9, ..., 1009 (127 chunks, steps t = 1..1016)
    for (int t0 = 1; t0 <= T_ - 15; t0 += 8) {
#pragma unroll
        for (int j = 0; j < 8; ++j) {
            const int t = t0 + j;
            CTC_STEP(t, e[j]);
            const int tn = t + 8;                // prefetch emission for t+8
            if (tn < T_) e[j] = LP[(size_t)tn * V_ + myext];
        }
    }
    // Tail: t = 1017..1023 (7 steps), emissions already in e[0..6]
#pragma unroll
    for (int j = 0; j < 7; ++j) {
        CTC_STEP(1017 + j, e[j]);
    }
#undef CTC_STEP

    if (act) afin[tid] = alpha;
    __syncthreads();

    if (tid == 0) {
        const int last = 2 * tlen[b];              // 32..256
        float aN  = afin[last];
        float aN1 = afin[last - 1];
        float m   = fmaxf(aN, aN1);
        g_loss[b] = -LN2_ * (m + __log2f(fexp2(aN - m) + fexp2(aN1 - m)));
    }
}

// ---------------------------------------------------------------------------
// Kernel 3: deterministic fixed-order sum of the 128 losses.
// ---------------------------------------------------------------------------
__global__ __launch_bounds__(128) void sum_kernel(float* __restrict__ out)
{
    __shared__ float s[128];
    const int t = threadIdx.x;
    s[t] = g_loss[t];
    __syncthreads();
    for (int o = 64; o > 0; o >>= 1) {
        if (t < o) s[t] += s[t + o];
        __syncthreads();
    }
    if (t == 0) out[0] = s[0];
}

extern "C" void kernel_launch(void* const* d_in, const int* in_sizes, int n_in,
                              void* d_out, int out_size)
{
    (void)in_sizes; (void)n_in; (void)out_size;
    const float* x       = (const float*)d_in[0];
    const float* W       = (const float*)d_in[1];
    const float* bias    = (const float*)d_in[2];
    const int*   targets = (const int*)d_in[3];
    const int*   tlength = (const int*)d_in[4];

    gemm_softmax_kernel<<<(B_ * T_) / BM, 256>>>(x, W, bias);
    ctc_kernel<<<B_, 288>>>(targets, tlength);
    sum_kernel<<<1, 128>>>((float*)d_out);
}

// round 10
// speedup vs baseline: 1.2875x; 1.2875x over previous
#include <cuda_runtime.h>
#include <cuda_bf16.h>
#include <math_constants.h>
#include <mma.h>

using namespace nvcuda;

// Problem constants
#define B_    128
#define T_    1024
#define D_    512
#define V_    128
#define L_    128
#define S_    257           // 2L+1
#define BLANK_ 127          // V-1
#define EPS_  1e-7f
#define NEG_  (-1e30f)
#define LN2_  0.6931471805599453f

// GEMM tiling
#define BM 128
#define BN 128
#define BK 32
#define NCHUNK (D_ / BK)    // 16
#define APAD 8
#define BPAD 8
#define CPAD 4

// Scratch: log2(softmax prob + eps) [B,T,V] fp32 (64 MB), per-example losses
static __device__ float g_lp[B_ * T_ * V_];
static __device__ float g_loss[B_];

__device__ __forceinline__ float fexp2(float x) {
    float y; asm("ex2.approx.ftz.f32 %0, %1;" : "=f"(y) : "f"(x)); return y;
}

__device__ __forceinline__ void st4bf16(__nv_bfloat16* dst, float4 v) {
    __nv_bfloat162 p0; p0.x = __float2bfloat16(v.x); p0.y = __float2bfloat16(v.y);
    __nv_bfloat162 p1; p1.x = __float2bfloat16(v.z); p1.y = __float2bfloat16(v.w);
    *(__nv_bfloat162*)(dst)     = p0;
    *(__nv_bfloat162*)(dst + 2) = p1;
}

// ---------------------------------------------------------------------------
// Kernel 1: bf16 WMMA GEMM (logits = X @ W + b) + softmax -> g_lp = log2(p+eps)
// M = 131072, N = 128, K = 512, fp32 accumulate. Register-staged 2-stage
// double buffer: per iteration, issue all 8 independent LDG.128 for chunk
// c+1 (MLP=8), MMA chunk c from smem, convert+STS chunk c+1, ONE barrier.
// Block 128x128, BK=32, 8 warps (4M x 2N), warp tile 32x64.
// ---------------------------------------------------------------------------
__global__ __launch_bounds__(256) void gemm_softmax_kernel(
    const float* __restrict__ X, const float* __restrict__ W,
    const float* __restrict__ bias)
{
    __shared__ union {
        struct {
            __nv_bfloat16 A[2][BM][BK + APAD];   // 2 x 128 x 40 bf16 = 20480 B
            __nv_bfloat16 Bm[2][BK][BN + BPAD];  // 2 x  32 x 136 bf16 = 17408 B
        } st;
        float Cs[32][BN + CPAD];                 // 16896 B (epilogue reuse)
    } smem;

    const int tid = threadIdx.x;
    const int wid = tid >> 5;
    const int warp_m = wid & 3;       // 0..3
    const int warp_n = wid >> 2;      // 0..1
    const int rowBase = blockIdx.x * BM;

    wmma::fragment<wmma::accumulator, 16, 16, 16, float> cfrag[2][4];
#pragma unroll
    for (int i = 0; i < 2; ++i)
#pragma unroll
        for (int j = 0; j < 4; ++j) wmma::fill_fragment(cfrag[i][j], 0.f);

    // Load mapping: A 128x32 (2 threads/row, 16 floats each);
    //               B  32x128 (8 threads/row, 16 floats each)
    const int ar = tid >> 1;
    const int ac = (tid & 1) * 16;
    const int br = tid >> 3;
    const int bc = (tid & 7) * 16;
    const float* Ap = X + (size_t)(rowBase + ar) * D_ + ac;
    const float* Bp = W + (size_t)br * V_ + bc;

    float4 ra[4], rb[4];
#define LOAD_REGS(K0)                                                       \
    {   const float* ap = Ap + (K0);                                        \
        const float* bp = Bp + (size_t)(K0) * V_;                           \
        ra[0] = *(const float4*)(ap);      ra[1] = *(const float4*)(ap + 4);\
        ra[2] = *(const float4*)(ap + 8);  ra[3] = *(const float4*)(ap + 12);\
        rb[0] = *(const float4*)(bp);      rb[1] = *(const float4*)(bp + 4);\
        rb[2] = *(const float4*)(bp + 8);  rb[3] = *(const float4*)(bp + 12); }
#define STORE_STAGE(P)                                                      \
    {   st4bf16(&smem.st.A[P][ar][ac + 0],  ra[0]);                         \
        st4bf16(&smem.st.A[P][ar][ac + 4],  ra[1]);                         \
        st4bf16(&smem.st.A[P][ar][ac + 8],  ra[2]);                         \
        st4bf16(&smem.st.A[P][ar][ac + 12], ra[3]);                         \
        st4bf16(&smem.st.Bm[P][br][bc + 0],  rb[0]);                        \
        st4bf16(&smem.st.Bm[P][br][bc + 4],  rb[1]);                        \
        st4bf16(&smem.st.Bm[P][br][bc + 8],  rb[2]);                        \
        st4bf16(&smem.st.Bm[P][br][bc + 12], rb[3]); }

    // Prologue: stage chunk 0
    LOAD_REGS(0);
    STORE_STAGE(0);
    __syncthreads();

    for (int c = 0; c < NCHUNK; ++c) {
        const int p = c & 1;
        if (c + 1 < NCHUNK) LOAD_REGS((c + 1) * BK);   // 8 independent LDG.128

#pragma unroll
        for (int kk = 0; kk < BK; kk += 16) {
            wmma::fragment<wmma::matrix_a, 16, 16, 16, __nv_bfloat16, wmma::row_major> af[2];
            wmma::fragment<wmma::matrix_b, 16, 16, 16, __nv_bfloat16, wmma::row_major> bf[4];
#pragma unroll
            for (int i = 0; i < 2; ++i)
                wmma::load_matrix_sync(af[i], &smem.st.A[p][warp_m * 32 + i * 16][kk], BK + APAD);
#pragma unroll
            for (int j = 0; j < 4; ++j)
                wmma::load_matrix_sync(bf[j], &smem.st.Bm[p][kk][warp_n * 64 + j * 16], BN + BPAD);
#pragma unroll
            for (int i = 0; i < 2; ++i)
#pragma unroll
                for (int j = 0; j < 4; ++j)
                    wmma::mma_sync(cfrag[i][j], af[i], bf[j], cfrag[i][j]);
        }

        if (c + 1 < NCHUNK) STORE_STAGE(p ^ 1);
        __syncthreads();
    }
#undef LOAD_REGS
#undef STORE_STAGE

    // Epilogue: 4 passes of 32 rows through Cs (aliases stage smem; all stage
    // reads completed at the loop's final barrier). Softmax, write log2(p+eps).
    const int tx = tid & 15;
    const int ty = tid >> 4;
    float bb[8];
#pragma unroll
    for (int j = 0; j < 8; ++j) bb[j] = bias[tx * 8 + j];

    for (int wm = 0; wm < 4; ++wm) {
        if (warp_m == wm) {
#pragma unroll
            for (int i = 0; i < 2; ++i)
#pragma unroll
                for (int j = 0; j < 4; ++j)
                    wmma::store_matrix_sync(&smem.Cs[i * 16][warp_n * 64 + j * 16],
                                            cfrag[i][j], BN + CPAD, wmma::mem_row_major);
        }
        __syncthreads();
#pragma unroll
        for (int r = 0; r < 2; ++r) {
            const int row = ty * 2 + r;
            float l[8];
            float rmax = -CUDART_INF_F;
#pragma unroll
            for (int j = 0; j < 8; ++j) {
                l[j] = smem.Cs[row][tx * 8 + j] + bb[j];
                rmax = fmaxf(rmax, l[j]);
            }
#pragma unroll
            for (int m = 1; m <= 8; m <<= 1)
                rmax = fmaxf(rmax, __shfl_xor_sync(0xFFFFFFFFu, rmax, m));
            float s = 0.f;
#pragma unroll
            for (int j = 0; j < 8; ++j) { l[j] = __expf(l[j] - rmax); s += l[j]; }
#pragma unroll
            for (int m = 1; m <= 8; m <<= 1)
                s += __shfl_xor_sync(0xFFFFFFFFu, s, m);
            float invs = 1.f / s;
            float* orow = g_lp + (size_t)(rowBase + wm * 32 + row) * V_ + tx * 8;
            float4 o0, o1;
            o0.x = __log2f(l[0] * invs + EPS_); o0.y = __log2f(l[1] * invs + EPS_);
            o0.z = __log2f(l[2] * invs + EPS_); o0.w = __log2f(l[3] * invs + EPS_);
            o1.x = __log2f(l[4] * invs + EPS_); o1.y = __log2f(l[5] * invs + EPS_);
            o1.z = __log2f(l[6] * invs + EPS_); o1.w = __log2f(l[7] * invs + EPS_);
            *(float4*)orow = o0;
            *(float4*)(orow + 4) = o1;
        }
        __syncthreads();
    }
}

// ---------------------------------------------------------------------------
// Kernel 2: CTC forward DP, log2 domain (R7 version — fastest measured).
// One block per example, 288 threads, thread s owns state s (<257). Each
// state thread loads its own emission lp[t][myext] directly from global into
// a statically-indexed 8-deep FIFO (t-loop unrolled by 8 -> true depth 8).
// ---------------------------------------------------------------------------
__global__ __launch_bounds__(288) void ctc_kernel(
    const int* __restrict__ targets, const int* __restrict__ tlen)
{
    __shared__ float alpha[2][S_];
    __shared__ int   exts[S_];

    const int b = blockIdx.x;
    const int tid = threadIdx.x;
    const bool act = (tid < S_);
    const float* LP = g_lp + (size_t)b * T_ * V_;

    if (act) exts[tid] = (tid & 1) ? targets[b * L_ + (tid >> 1)] : BLANK_;
    __syncthreads();

    int  myext  = BLANK_;
    bool allow2 = false;
    if (act) {
        myext  = exts[tid];
        allow2 = (tid & 1) && (tid >= 2) && (myext != exts[tid - 2]);
    }

    // t = 0 init + prefetch FIFO for t = 1..8
    if (act) alpha[0][tid] = (tid < 2) ? LP[myext] : NEG_;
    float e[8];
#pragma unroll
    for (int j = 0; j < 8; ++j) e[j] = LP[(size_t)(1 + j) * V_ + myext];
    __syncthreads();

    // Main chunks: t0 = 1, 9, ..., 1009 (127 chunks, steps t = 1..1016).
    for (int t0 = 1; t0 <= T_ - 15; t0 += 8) {
#pragma unroll
        for (int j = 0; j < 8; ++j) {
            const int cur  = (1 + j) & 1;     // t0 odd -> parity is (1+j)&1
            const int prev = cur ^ 1;
            if (act) {
                float a  = alpha[prev][tid];
                float a1 = (tid >= 1) ? alpha[prev][tid - 1] : NEG_;
                float a2 = allow2 ? alpha[prev][tid - 2] : NEG_;
                float m  = fmaxf(fmaxf(a, a1), a2);
                float s  = fexp2(a - m) + fexp2(a1 - m) + fexp2(a2 - m);
                alpha[cur][tid] = m + __log2f(s) + e[j];
            }
            const int tn = t0 + 8 + j;        // prefetch for step t0+8+j
            if (tn < T_) e[j] = LP[(size_t)tn * V_ + myext];
            __syncthreads();
        }
    }
    // Tail: t = 1017..1023 (7 steps), emissions already in e[0..6].
#pragma unroll
    for (int j = 0; j < 7; ++j) {
        const int cur  = (1017 + j) & 1;
        const int prev = cur ^ 1;
        if (act) {
            float a  = alpha[prev][tid];
            float a1 = (tid >= 1) ? alpha[prev][tid - 1] : NEG_;
            float a2 = allow2 ? alpha[prev][tid - 2] : NEG_;
            float m  = fmaxf(fmaxf(a, a1), a2);
            float s  = fexp2(a - m) + fexp2(a1 - m) + fexp2(a2 - m);
            alpha[cur][tid] = m + __log2f(s) + e[j];
        }
        __syncthreads();
    }

    if (tid == 0) {
        const int last = 2 * tlen[b];              // 32..256
        // t = 1023 is odd -> final alpha lives in buffer 1.
        float aN  = alpha[1][last];
        float aN1 = alpha[1][last - 1];
        float m   = fmaxf(aN, aN1);
        g_loss[b] = -LN2_ * (m + __log2f(fexp2(aN - m) + fexp2(aN1 - m)));
    }
}

// ---------------------------------------------------------------------------
// Kernel 3: deterministic fixed-order sum of the 128 losses.
// ---------------------------------------------------------------------------
__global__ __launch_bounds__(128) void sum_kernel(float* __restrict__ out)
{
    __shared__ float s[128];
    const int t = threadIdx.x;
    s[t] = g_loss[t];
    __syncthreads();
    for (int o = 64; o > 0; o >>= 1) {
        if (t < o) s[t] += s[t + o];
        __syncthreads();
    }
    if (t == 0) out[0] = s[0];
}

extern "C" void kernel_launch(void* const* d_in, const int* in_sizes, int n_in,
                              void* d_out, int out_size)
{
    (void)in_sizes; (void)n_in; (void)out_size;
    const float* x       = (const float*)d_in[0];
    const float* W       = (const float*)d_in[1];
    const float* bias    = (const float*)d_in[2];
    const int*   targets = (const int*)d_in[3];
    const int*   tlength = (const int*)d_in[4];

    gemm_softmax_kernel<<<(B_ * T_) / BM, 256>>>(x, W, bias);
    ctc_kernel<<<B_, 288>>>(targets, tlength);
    sum_kernel<<<1, 128>>>((float*)d_out);
}

// round 11
// speedup vs baseline: 1.2959x; 1.0065x over previous
#include <cuda_runtime.h>
#include <cuda_bf16.h>
#include <math_constants.h>
#include <mma.h>

using namespace nvcuda;

// Problem constants
#define B_    128
#define T_    1024
#define D_    512
#define V_    128
#define L_    128
#define S_    257           // 2L+1
#define BLANK_ 127          // V-1
#define EPS_  1e-7f
#define NEG_  (-1e30f)
#define LN2_  0.6931471805599453f

// GEMM tiling
#define BM 128
#define BN 128
#define BK 16
#define NCHUNK (D_ / BK)    // 32
#define AFPAD 4             // fp32 stage pads
#define BFPAD 4
#define ABPAD 8             // bf16 buffer pads
#define BBPAD 8
#define CPAD 4

// Scratch: log2(softmax prob + eps) [B,T,V] fp32 (64 MB), per-example losses
static __device__ float g_lp[B_ * T_ * V_];
static __device__ float g_loss[B_];

__device__ __forceinline__ float fexp2(float x) {
    float y; asm("ex2.approx.ftz.f32 %0, %1;" : "=f"(y) : "f"(x)); return y;
}

__device__ __forceinline__ void st4bf16(__nv_bfloat16* dst, float4 v) {
    __nv_bfloat162 p0; p0.x = __float2bfloat16(v.x); p0.y = __float2bfloat16(v.y);
    __nv_bfloat162 p1; p1.x = __float2bfloat16(v.z); p1.y = __float2bfloat16(v.w);
    *(__nv_bfloat162*)(dst)     = p0;
    *(__nv_bfloat162*)(dst + 2) = p1;
}

__device__ __forceinline__ void cp16(void* dst_smem, const void* src) {
    unsigned d = (unsigned)__cvta_generic_to_shared(dst_smem);
    asm volatile("cp.async.ca.shared.global [%0], [%1], 16;\n" :: "r"(d), "l"(src));
}

// ---------------------------------------------------------------------------
// Kernel 1: bf16 WMMA GEMM (logits = X @ W + b) + softmax -> g_lp = log2(p+eps)
// M = 131072, N = 128, K = 512, fp32 accumulate.
// cp.async streams RAW fp32 into a 2-stage smem buffer (no registers on the
// load path -> DRAM runs at service rate); a per-chunk in-smem convert pass
// produces bf16 tiles for the fast bf16 HMMA path. Block 128x128, BK=16,
// 8 warps (4M x 2N), warp tile 32x64.
// ---------------------------------------------------------------------------
__global__ __launch_bounds__(256) void gemm_softmax_kernel(
    const float* __restrict__ X, const float* __restrict__ W,
    const float* __restrict__ bias)
{
    __shared__ __align__(16) union {
        struct {
            float Afp[2][BM][BK + AFPAD];        // 2*128*20*4 = 20480 B
            float Bfp[2][BK][BN + BFPAD];        // 2*16*132*4 = 16896 B
            __nv_bfloat16 Ab[BM][BK + ABPAD];    // 128*24*2   =  6144 B
            __nv_bfloat16 Bb[BK][BN + BBPAD];    // 16*136*2   =  4352 B
        } st;                                    // 47872 B (< 48 KB)
        float Cs[32][BN + CPAD];                 // 16896 B (epilogue reuse)
    } smem;

    const int tid = threadIdx.x;
    const int wid = tid >> 5;
    const int warp_m = wid & 3;       // 0..3
    const int warp_n = wid >> 2;      // 0..1
    const int rowBase = blockIdx.x * BM;

    wmma::fragment<wmma::accumulator, 16, 16, 16, float> cfrag[2][4];
#pragma unroll
    for (int i = 0; i < 2; ++i)
#pragma unroll
        for (int j = 0; j < 4; ++j) wmma::fill_fragment(cfrag[i][j], 0.f);

    // cp.async / convert mapping:
    //  A chunk 128x16 fp32: row = tid>>1, col = (tid&1)*8  (8 floats/thread)
    //  B chunk  16x128 fp32: row = tid>>4, col = (tid&15)*8
    const int ar = tid >> 1;
    const int ac = (tid & 1) * 8;
    const int br = tid >> 4;
    const int bc = (tid & 15) * 8;
    const float* Ap = X + (size_t)(rowBase + ar) * D_ + ac;
    const float* Bp = W + (size_t)br * V_ + bc;

#define ISSUE_CHUNK(C, P)                                                     \
    {   const int k0 = (C) * BK;                                              \
        cp16(&smem.st.Afp[P][ar][ac],     Ap + k0);                           \
        cp16(&smem.st.Afp[P][ar][ac + 4], Ap + k0 + 4);                       \
        cp16(&smem.st.Bfp[P][br][bc],     Bp + (size_t)k0 * V_);              \
        cp16(&smem.st.Bfp[P][br][bc + 4], Bp + (size_t)k0 * V_ + 4); }

    // Prologue: issue chunks 0 and 1
    ISSUE_CHUNK(0, 0); asm volatile("cp.async.commit_group;\n");
    ISSUE_CHUNK(1, 1); asm volatile("cp.async.commit_group;\n");

    for (int c = 0; c < NCHUNK; ++c) {
        const int p = c & 1;
        asm volatile("cp.async.wait_group 1;\n");   // stage p (chunk c) ready
        __syncthreads();   // also orders prior MMA reads of Ab/Bb before rewrite

        // Convert fp32 stage -> bf16 tiles
        {
            float4 a0 = *(const float4*)&smem.st.Afp[p][ar][ac];
            float4 a1 = *(const float4*)&smem.st.Afp[p][ar][ac + 4];
            float4 b0 = *(const float4*)&smem.st.Bfp[p][br][bc];
            float4 b1 = *(const float4*)&smem.st.Bfp[p][br][bc + 4];
            st4bf16(&smem.st.Ab[ar][ac],     a0);
            st4bf16(&smem.st.Ab[ar][ac + 4], a1);
            st4bf16(&smem.st.Bb[br][bc],     b0);
            st4bf16(&smem.st.Bb[br][bc + 4], b1);
        }
        __syncthreads();

        // Refill stage p with chunk c+2 (its fp32 was fully consumed above)
        if (c + 2 < NCHUNK) ISSUE_CHUNK(c + 2, p);
        asm volatile("cp.async.commit_group;\n");   // empty group keeps counts uniform

        // MMA on bf16 tiles (BK=16 -> single k-step)
        wmma::fragment<wmma::matrix_a, 16, 16, 16, __nv_bfloat16, wmma::row_major> af[2];
        wmma::fragment<wmma::matrix_b, 16, 16, 16, __nv_bfloat16, wmma::row_major> bf[4];
#pragma unroll
        for (int i = 0; i < 2; ++i)
            wmma::load_matrix_sync(af[i], &smem.st.Ab[warp_m * 32 + i * 16][0], BK + ABPAD);
#pragma unroll
        for (int j = 0; j < 4; ++j)
            wmma::load_matrix_sync(bf[j], &smem.st.Bb[0][warp_n * 64 + j * 16], BN + BBPAD);
#pragma unroll
        for (int i = 0; i < 2; ++i)
#pragma unroll
            for (int j = 0; j < 4; ++j)
                wmma::mma_sync(cfrag[i][j], af[i], bf[j], cfrag[i][j]);
    }
#undef ISSUE_CHUNK
    __syncthreads();   // all MMA reads done before Cs aliases the stage smem

    // Epilogue: 4 passes of 32 rows through Cs. Softmax, write log2(p+eps).
    const int tx = tid & 15;
    const int ty = tid >> 4;
    float bb[8];
#pragma unroll
    for (int j = 0; j < 8; ++j) bb[j] = bias[tx * 8 + j];

    for (int wm = 0; wm < 4; ++wm) {
        if (warp_m == wm) {
#pragma unroll
            for (int i = 0; i < 2; ++i)
#pragma unroll
                for (int j = 0; j < 4; ++j)
                    wmma::store_matrix_sync(&smem.Cs[i * 16][warp_n * 64 + j * 16],
                                            cfrag[i][j], BN + CPAD, wmma::mem_row_major);
        }
        __syncthreads();
#pragma unroll
        for (int r = 0; r < 2; ++r) {
            const int row = ty * 2 + r;
            float l[8];
            float rmax = -CUDART_INF_F;
#pragma unroll
            for (int j = 0; j < 8; ++j) {
                l[j] = smem.Cs[row][tx * 8 + j] + bb[j];
                rmax = fmaxf(rmax, l[j]);
            }
#pragma unroll
            for (int m = 1; m <= 8; m <<= 1)
                rmax = fmaxf(rmax, __shfl_xor_sync(0xFFFFFFFFu, rmax, m));
            float s = 0.f;
#pragma unroll
            for (int j = 0; j < 8; ++j) { l[j] = __expf(l[j] - rmax); s += l[j]; }
#pragma unroll
            for (int m = 1; m <= 8; m <<= 1)
                s += __shfl_xor_sync(0xFFFFFFFFu, s, m);
            float invs = 1.f / s;
            float* orow = g_lp + (size_t)(rowBase + wm * 32 + row) * V_ + tx * 8;
            float4 o0, o1;
            o0.x = __log2f(l[0] * invs + EPS_); o0.y = __log2f(l[1] * invs + EPS_);
            o0.z = __log2f(l[2] * invs + EPS_); o0.w = __log2f(l[3] * invs + EPS_);
            o1.x = __log2f(l[4] * invs + EPS_); o1.y = __log2f(l[5] * invs + EPS_);
            o1.z = __log2f(l[6] * invs + EPS_); o1.w = __log2f(l[7] * invs + EPS_);
            *(float4*)orow = o0;
            *(float4*)(orow + 4) = o1;
        }
        __syncthreads();
    }
}

// ---------------------------------------------------------------------------
// Kernel 2: CTC forward DP, log2 domain (R7 version — fastest measured).
// One block per example, 288 threads, thread s owns state s (<257). Each
// state thread loads its own emission lp[t][myext] directly from global into
// a statically-indexed 8-deep FIFO (t-loop unrolled by 8 -> true depth 8).
// ---------------------------------------------------------------------------
__global__ __launch_bounds__(288) void ctc_kernel(
    const int* __restrict__ targets, const int* __restrict__ tlen)
{
    __shared__ float alpha[2][S_];
    __shared__ int   exts[S_];

    const int b = blockIdx.x;
    const int tid = threadIdx.x;
    const bool act = (tid < S_);
    const float* LP = g_lp + (size_t)b * T_ * V_;

    if (act) exts[tid] = (tid & 1) ? targets[b * L_ + (tid >> 1)] : BLANK_;
    __syncthreads();

    int  myext  = BLANK_;
    bool allow2 = false;
    if (act) {
        myext  = exts[tid];
        allow2 = (tid & 1) && (tid >= 2) && (myext != exts[tid - 2]);
    }

    // t = 0 init + prefetch FIFO for t = 1..8
    if (act) alpha[0][tid] = (tid < 2) ? LP[myext] : NEG_;
    float e[8];
#pragma unroll
    for (int j = 0; j < 8; ++j) e[j] = LP[(size_t)(1 + j) * V_ + myext];
    __syncthreads();

    // Main chunks: t0 = 1, 9, ..., 1009 (127 chunks, steps t = 1..1016).
    for (int t0 = 1; t0 <= T_ - 15; t0 += 8) {
#pragma unroll
        for (int j = 0; j < 8; ++j) {
            const int cur  = (1 + j) & 1;     // t0 odd -> parity is (1+j)&1
            const int prev = cur ^ 1;
            if (act) {
                float a  = alpha[prev][tid];
                float a1 = (tid >= 1) ? alpha[prev][tid - 1] : NEG_;
                float a2 = allow2 ? alpha[prev][tid - 2] : NEG_;
                float m  = fmaxf(fmaxf(a, a1), a2);
                float s  = fexp2(a - m) + fexp2(a1 - m) + fexp2(a2 - m);
                alpha[cur][tid] = m + __log2f(s) + e[j];
            }
            const int tn = t0 + 8 + j;        // prefetch for step t0+8+j
            if (tn < T_) e[j] = LP[(size_t)tn * V_ + myext];
            __syncthreads();
        }
    }
    // Tail: t = 1017..1023 (7 steps), emissions already in e[0..6].
#pragma unroll
    for (int j = 0; j < 7; ++j) {
        const int cur  = (1017 + j) & 1;
        const int prev = cur ^ 1;
        if (act) {
            float a  = alpha[prev][tid];
            float a1 = (tid >= 1) ? alpha[prev][tid - 1] : NEG_;
            float a2 = allow2 ? alpha[prev][tid - 2] : NEG_;
            float m  = fmaxf(fmaxf(a, a1), a2);
            float s  = fexp2(a - m) + fexp2(a1 - m) + fexp2(a2 - m);
            alpha[cur][tid] = m + __log2f(s) + e[j];
        }
        __syncthreads();
    }

    if (tid == 0) {
        const int last = 2 * tlen[b];              // 32..256
        // t = 1023 is odd -> final alpha lives in buffer 1.
        float aN  = alpha[1][last];
        float aN1 = alpha[1][last - 1];
        float m   = fmaxf(aN, aN1);
        g_loss[b] = -LN2_ * (m + __log2f(fexp2(aN - m) + fexp2(aN1 - m)));
    }
}

// ---------------------------------------------------------------------------
// Kernel 3: deterministic fixed-order sum of the 128 losses.
// ---------------------------------------------------------------------------
__global__ __launch_bounds__(128) void sum_kernel(float* __restrict__ out)
{
    __shared__ float s[128];
    const int t = threadIdx.x;
    s[t] = g_loss[t];
    __syncthreads();
    for (int o = 64; o > 0; o >>= 1) {
        if (t < o) s[t] += s[t + o];
        __syncthreads();
    }
    if (t == 0) out[0] = s[0];
}

extern "C" void kernel_launch(void* const* d_in, const int* in_sizes, int n_in,
                              void* d_out, int out_size)
{
    (void)in_sizes; (void)n_in; (void)out_size;
    const float* x       = (const float*)d_in[0];
    const float* W       = (const float*)d_in[1];
    const float* bias    = (const float*)d_in[2];
    const int*   targets = (const int*)d_in[3];
    const int*   tlength = (const int*)d_in[4];

    gemm_softmax_kernel<<<(B_ * T_) / BM, 256>>>(x, W, bias);
    ctc_kernel<<<B_, 288>>>(targets, tlength);
    sum_kernel<<<1, 128>>>((float*)d_out);
}